// round 4
// baseline (speedup 1.0000x reference)
#include <cuda_runtime.h>
#include <cstdint>

// out[b, g, k, c] = textures[b, group_idx[g, k], c]
// B=2, T=1e6, C=16 (fp32), G=500000, K=9.
//
// R4: batch-sequential dispatch. R3 ncu showed DRAM traffic stuck at ~935MB:
// grid.y=2 co-scheduled both batches, so the combined gather working set
// (2 x 64MB textures) exceeded L2 (126MB) and thrashed. Now a 1D grid puts
// all batch-0 blocks at low bids -> dispatched first -> live working set is
// one 64MB texture, which stays L2-resident (writes are evict-first __stcs).
// Keeps R3's U=8 three-phase MLP structure.

#define U 8

__global__ void __launch_bounds__(256)
tmscnn_gather_kernel(const float4* __restrict__ tex,     // [B, T*C/4]
                     const int*    __restrict__ gidx,    // [G*K]
                     float4*       __restrict__ out,     // [B, G*K*4]
                     int total_f4,                       // G*K*4
                     int blocks_per_batch,
                     long long tex_batch_stride_f4,      // T*C/4
                     long long out_batch_stride_f4)      // G*K*4
{
    // Batch 0 occupies block ids [0, blocks_per_batch), batch 1 the rest.
    int bid = blockIdx.x;
    int b = 0;
    if (bid >= blocks_per_batch) { b = 1; bid -= blocks_per_batch; }

    const int stride = blocks_per_batch * blockDim.x;
    const int i0 = bid * blockDim.x + threadIdx.x;

    const float4* tex_b = tex + (long long)b * tex_batch_stride_f4;
    float4*       out_b = out + (long long)b * out_batch_stride_f4;

    int    ii[U];
    int    tt[U];
    float4 vv[U];

    // Phase 1: independent index loads
    #pragma unroll
    for (int u = 0; u < U; u++) {
        ii[u] = i0 + u * stride;
        tt[u] = 0;
        if (ii[u] < total_f4)
            tt[u] = __ldg(gidx + (ii[u] >> 2));
    }

    // Phase 2: independent texel gathers (MLP = U)
    #pragma unroll
    for (int u = 0; u < U; u++) {
        if (ii[u] < total_f4)
            vv[u] = __ldg(tex_b + (long long)tt[u] * 4 + (ii[u] & 3));
    }

    // Phase 3: streaming stores (evict-first; protect texture residency)
    #pragma unroll
    for (int u = 0; u < U; u++) {
        if (ii[u] < total_f4)
            __stcs(out_b + ii[u], vv[u]);
    }
}

extern "C" void kernel_launch(void* const* d_in, const int* in_sizes, int n_in,
                              void* d_out, int out_size)
{
    // metadata order: mesh_ids [B] int32, textures [B,T,C] f32, group_idx [G,K] int32
    const float* textures = (const float*)d_in[1];
    const int*   gidx     = (const int*)d_in[2];
    float*       out      = (float*)d_out;

    int B  = in_sizes[0];             // 2
    int GK = in_sizes[2];             // G*K = 4,500,000
    long long TC = (long long)in_sizes[1] / B;   // T*C = 16,000,000

    int total_f4 = GK * 4;            // 18,000,000 elements per batch
    long long tex_stride_f4 = TC / 4; // 4,000,000
    long long out_stride_f4 = (long long)GK * 4;

    int threads_per_batch = (total_f4 + U - 1) / U;
    int blocks_per_batch  = (threads_per_batch + 255) / 256;

    dim3 block(256);
    dim3 grid(blocks_per_batch * B);

    tmscnn_gather_kernel<<<grid, block>>>(
        (const float4*)textures, gidx, (float4*)out,
        total_f4, blocks_per_batch, tex_stride_f4, out_stride_f4);
}

// round 5
// speedup vs baseline: 1.0732x; 1.0732x over previous
#include <cuda_runtime.h>
#include <cstdint>

// out[b, g, k, c] = textures[b, group_idx[g, k], c]
// B=2, T=1e6, C=16 (fp32), G=500000, K=9.
//
// R5: R3 structure (best: 184us) with stores changed __stcs -> __stwt.
// Evidence: DRAM traffic pinned at ~930MB across R2-R4 even when only one
// 64MB texture was live vs 126MB L2 => output write allocation is evicting
// the texture (__stcs insufficient). st.global.wt writes through without
// establishing resident lines; warp stores are 512B contiguous so the MC
// still sees full-line bursts. Everything else identical to R3.

#define U 8

__global__ void __launch_bounds__(256)
tmscnn_gather_kernel(const float4* __restrict__ tex,     // [B, T*C/4]
                     const int*    __restrict__ gidx,    // [G*K]
                     float4*       __restrict__ out,     // [B, G*K*4]
                     int total_f4,                       // G*K*4
                     long long tex_batch_stride_f4,      // T*C/4
                     long long out_batch_stride_f4)      // G*K*4
{
    const int stride = gridDim.x * blockDim.x;
    const int i0 = blockIdx.x * blockDim.x + threadIdx.x;
    const int b = blockIdx.y;

    const float4* tex_b = tex + (long long)b * tex_batch_stride_f4;
    float4*       out_b = out + (long long)b * out_batch_stride_f4;

    int    ii[U];
    int    tt[U];
    float4 vv[U];

    // Phase 1: independent index loads
    #pragma unroll
    for (int u = 0; u < U; u++) {
        ii[u] = i0 + u * stride;
        tt[u] = 0;
        if (ii[u] < total_f4)
            tt[u] = __ldg(gidx + (ii[u] >> 2));
    }

    // Phase 2: independent texel gathers (MLP = U)
    #pragma unroll
    for (int u = 0; u < U; u++) {
        if (ii[u] < total_f4)
            vv[u] = __ldg(tex_b + (long long)tt[u] * 4 + (ii[u] & 3));
    }

    // Phase 3: write-through stores (no L2 allocation -> texture stays resident)
    #pragma unroll
    for (int u = 0; u < U; u++) {
        if (ii[u] < total_f4)
            __stwt(out_b + ii[u], vv[u]);
    }
}

extern "C" void kernel_launch(void* const* d_in, const int* in_sizes, int n_in,
                              void* d_out, int out_size)
{
    // metadata order: mesh_ids [B] int32, textures [B,T,C] f32, group_idx [G,K] int32
    const float* textures = (const float*)d_in[1];
    const int*   gidx     = (const int*)d_in[2];
    float*       out      = (float*)d_out;

    int B  = in_sizes[0];             // 2
    int GK = in_sizes[2];             // G*K = 4,500,000
    long long TC = (long long)in_sizes[1] / B;   // T*C = 16,000,000

    int total_f4 = GK * 4;            // 18,000,000 elements per batch
    long long tex_stride_f4 = TC / 4; // 4,000,000
    long long out_stride_f4 = (long long)GK * 4;

    int threads_needed = (total_f4 + U - 1) / U;
    dim3 block(256);
    dim3 grid((threads_needed + 255) / 256, B);

    tmscnn_gather_kernel<<<grid, block>>>(
        (const float4*)textures, gidx, (float4*)out,
        total_f4, tex_stride_f4, out_stride_f4);
}

// round 7
// speedup vs baseline: 1.1367x; 1.0591x over previous
#include <cuda_runtime.h>
#include <cstdint>

// out[b, g, k, c] = textures[b, group_idx[g, k], c]
// B=2, T=1e6, C=16 (fp32), G=500000, K=9.
//
// R7: retry R6's L2::evict_last with the ptxas-required 256-bit shape
// (ld.global.nc.L2::evict_last.v4.b64). One thread now moves a 32B
// half-texel: gk = i>>1, half = i&1. Bonus independent of cache policy:
// half the gather/idx instruction count per byte vs R3. Stores stay
// evict-first (st.global.cs.v2.b64 x2, fully coalesced). U=4 keeps the
// same 128B-in-flight per thread as R3's U=8 at similar register cost.

#define U 4

__device__ __forceinline__ void ldg256_evict_last(const float4* p, unsigned long long d[4]) {
    asm volatile("ld.global.nc.L2::evict_last.v4.b64 {%0,%1,%2,%3}, [%4];"
                 : "=l"(d[0]), "=l"(d[1]), "=l"(d[2]), "=l"(d[3])
                 : "l"(p));
}

__device__ __forceinline__ void stg128_cs(float4* p, unsigned long long d0, unsigned long long d1) {
    asm volatile("st.global.cs.v2.b64 [%0], {%1,%2};"
                 :: "l"(p), "l"(d0), "l"(d1) : "memory");
}

__global__ void __launch_bounds__(256)
tmscnn_gather_kernel(const float4* __restrict__ tex,     // [B, T*C/4]
                     const int*    __restrict__ gidx,    // [G*K]
                     float4*       __restrict__ out,     // [B, G*K*4]
                     int total32,                        // G*K*2 (32B chunks)
                     long long tex_batch_stride_f4,      // T*C/4
                     long long out_batch_stride_f4)      // G*K*4
{
    const int stride = gridDim.x * blockDim.x;
    const int i0 = blockIdx.x * blockDim.x + threadIdx.x;
    const int b = blockIdx.y;

    const float4* tex_b = tex + (long long)b * tex_batch_stride_f4;
    float4*       out_b = out + (long long)b * out_batch_stride_f4;

    int ii[U];
    int tt[U];
    unsigned long long vv[U][4];

    // Phase 1: independent index loads (2 lanes share one idx)
    #pragma unroll
    for (int u = 0; u < U; u++) {
        ii[u] = i0 + u * stride;
        tt[u] = 0;
        if (ii[u] < total32)
            tt[u] = __ldg(gidx + (ii[u] >> 1));
    }

    // Phase 2: independent 32B gathers, LDG.256 with L2 evict_last
    #pragma unroll
    for (int u = 0; u < U; u++) {
        if (ii[u] < total32) {
            const float4* src = tex_b + (long long)tt[u] * 4 + (ii[u] & 1) * 2;
            ldg256_evict_last(src, vv[u]);
        }
    }

    // Phase 3: evict-first streaming stores (2 x 16B contiguous per thread)
    #pragma unroll
    for (int u = 0; u < U; u++) {
        if (ii[u] < total32) {
            float4* dst = out_b + (long long)ii[u] * 2;
            stg128_cs(dst,     vv[u][0], vv[u][1]);
            stg128_cs(dst + 1, vv[u][2], vv[u][3]);
        }
    }
}

extern "C" void kernel_launch(void* const* d_in, const int* in_sizes, int n_in,
                              void* d_out, int out_size)
{
    // metadata order: mesh_ids [B] int32, textures [B,T,C] f32, group_idx [G,K] int32
    const float* textures = (const float*)d_in[1];
    const int*   gidx     = (const int*)d_in[2];
    float*       out      = (float*)d_out;

    int B  = in_sizes[0];             // 2
    int GK = in_sizes[2];             // G*K = 4,500,000
    long long TC = (long long)in_sizes[1] / B;   // T*C = 16,000,000

    int total32 = GK * 2;             // 9,000,000 32B chunks per batch
    long long tex_stride_f4 = TC / 4; // 4,000,000
    long long out_stride_f4 = (long long)GK * 4;

    int threads_needed = (total32 + U - 1) / U;
    dim3 block(256);
    dim3 grid((threads_needed + 255) / 256, B);

    tmscnn_gather_kernel<<<grid, block>>>(
        (const float4*)textures, gidx, (float4*)out,
        total32, tex_stride_f4, out_stride_f4);
}

// round 8
// speedup vs baseline: 1.2051x; 1.0602x over previous
#include <cuda_runtime.h>
#include <cstdint>

// out[b, g, k, c] = textures[b, group_idx[g, k], c]
// B=2, T=1e6, C=16 (fp32), G=500000, K=9.
//
// R8: rate-focused. Traffic is invariant (~940MB) across all cache policies
// (R2-R7) => stop fighting hit-rate; raise concurrency and cut LTS requests.
//  - U=3 (24 data regs) + __launch_bounds__(256,6): <=40 regs -> 6 CTAs/SM
//    (75% occ vs 54.6%), +37% warps for latency/store overlap.
//  - Stores: single st.global.cs.v4.b64 (STG.256) per 32B chunk -> halves
//    store transactions into LTS.
//  - Loads stay ld.global.nc.L2::evict_last.v4.b64 (best-so-far R7 config).

#define U 3

__device__ __forceinline__ void ldg256_evict_last(const float4* p, unsigned long long d[4]) {
    asm volatile("ld.global.nc.L2::evict_last.v4.b64 {%0,%1,%2,%3}, [%4];"
                 : "=l"(d[0]), "=l"(d[1]), "=l"(d[2]), "=l"(d[3])
                 : "l"(p));
}

__device__ __forceinline__ void stg256_cs(float4* p, const unsigned long long d[4]) {
    asm volatile("st.global.cs.v4.b64 [%0], {%1,%2,%3,%4};"
                 :: "l"(p), "l"(d[0]), "l"(d[1]), "l"(d[2]), "l"(d[3]) : "memory");
}

__global__ void __launch_bounds__(256, 6)
tmscnn_gather_kernel(const float4* __restrict__ tex,     // [B, T*C/4]
                     const int*    __restrict__ gidx,    // [G*K]
                     float4*       __restrict__ out,     // [B, G*K*4]
                     int total32,                        // G*K*2 (32B chunks)
                     long long tex_batch_stride_f4,      // T*C/4
                     long long out_batch_stride_f4)      // G*K*4
{
    const int stride = gridDim.x * blockDim.x;
    const int i0 = blockIdx.x * blockDim.x + threadIdx.x;
    const int b = blockIdx.y;

    const float4* tex_b = tex + (long long)b * tex_batch_stride_f4;
    float4*       out_b = out + (long long)b * out_batch_stride_f4;

    int ii[U];
    int tt[U];
    unsigned long long vv[U][4];

    // Phase 1: independent index loads (2 lanes share one idx)
    #pragma unroll
    for (int u = 0; u < U; u++) {
        ii[u] = i0 + u * stride;
        tt[u] = 0;
        if (ii[u] < total32)
            tt[u] = __ldg(gidx + (ii[u] >> 1));
    }

    // Phase 2: independent 32B gathers, LDG.256 with L2 evict_last
    #pragma unroll
    for (int u = 0; u < U; u++) {
        if (ii[u] < total32) {
            const float4* src = tex_b + (long long)tt[u] * 4 + (ii[u] & 1) * 2;
            ldg256_evict_last(src, vv[u]);
        }
    }

    // Phase 3: evict-first streaming stores, one STG.256 per chunk
    #pragma unroll
    for (int u = 0; u < U; u++) {
        if (ii[u] < total32)
            stg256_cs(out_b + (long long)ii[u] * 2, vv[u]);
    }
}

extern "C" void kernel_launch(void* const* d_in, const int* in_sizes, int n_in,
                              void* d_out, int out_size)
{
    // metadata order: mesh_ids [B] int32, textures [B,T,C] f32, group_idx [G,K] int32
    const float* textures = (const float*)d_in[1];
    const int*   gidx     = (const int*)d_in[2];
    float*       out      = (float*)d_out;

    int B  = in_sizes[0];             // 2
    int GK = in_sizes[2];             // G*K = 4,500,000
    long long TC = (long long)in_sizes[1] / B;   // T*C = 16,000,000

    int total32 = GK * 2;             // 9,000,000 32B chunks per batch
    long long tex_stride_f4 = TC / 4; // 4,000,000
    long long out_stride_f4 = (long long)GK * 4;

    int threads_needed = (total32 + U - 1) / U;
    dim3 block(256);
    dim3 grid((threads_needed + 255) / 256, B);

    tmscnn_gather_kernel<<<grid, block>>>(
        (const float4*)textures, gidx, (float4*)out,
        total32, tex_stride_f4, out_stride_f4);
}